// round 12
// baseline (speedup 1.0000x reference)
#include <cuda_runtime.h>
#include <cstdint>

#define L1D 4096
#define L2D 4096
#define NB 8
#define CC 3
#define TOT (NB * L2D)      // 32768 outputs per half
#define G 16
#define NC (G * G * G)      // 4096 cells
#define BIN_THREADS 512
#define REFS_PER_T (L1D / BIN_THREADS)  // 8
#define S_THREADS 256       // 8 warps per CTA
#define QSPLIT 32
#define QCH (L2D / QSPLIT)  // 128 queries per CTA
#define QPW (QCH / (S_THREADS / 32))    // 16 queries per warp

// Binned refs per batch: (x, y, z, oidx-bits) + cell starts.
__device__ float4         g_ref4[NB][L1D];
__device__ unsigned short g_cs[NB][NC + 1];

// Proven bit-exact XLA chain (rounds 8/10/11 passed with rel_err 0.0):
//   sr/sq = fl(fl(x*x + y*y) + z*z)     (mul/add, NO fma)
//   dot   = fma(qz,rz, fma(qy,ry, mul(qx,rx)))
//   d2    = fma(dot, -2, add(sq, sr))
static __device__ __forceinline__ float sumsq(float x, float y, float z) {
    return __fadd_rn(__fadd_rn(__fmul_rn(x, x), __fmul_rn(y, y)),
                     __fmul_rn(z, z));
}
static __device__ __forceinline__ float d2ref(float qx, float qy, float qz,
                                              float sq, float rx, float ry,
                                              float rz, float sr) {
    const float dot = __fmaf_rn(qz, rz, __fmaf_rn(qy, ry, __fmul_rn(qx, rx)));
    return __fmaf_rn(dot, -2.0f, __fadd_rn(sq, sr));
}
static __device__ __forceinline__ int cell_of(float x, float y, float z) {
    int cx = min(G - 1, max(0, (int)(x * (float)G)));
    int cy = min(G - 1, max(0, (int)(y * (float)G)));
    int cz = min(G - 1, max(0, (int)(z * (float)G)));
    return (cz * G + cy) * G + cx;
}

// Kernel 1: per-batch counting sort of refs into 16^3 cells (one CTA/batch).
// Scatter order is atomic-order-dependent but the FINAL OUTPUT is invariant
// (argmin with original-index tie-break is order-independent).
__global__ __launch_bounds__(BIN_THREADS)
void nn_bin(const float* __restrict__ c1) {
    __shared__ unsigned int hist[NC];
    __shared__ unsigned int wsum[BIN_THREADS / 32];
    const int n = blockIdx.x;
    const int t = threadIdx.x;

    for (int i = t; i < NC; i += BIN_THREADS) hist[i] = 0;
    __syncthreads();

    float x[REFS_PER_T], y[REFS_PER_T], z[REFS_PER_T];
    int cell[REFS_PER_T];
#pragma unroll
    for (int k = 0; k < REFS_PER_T; k++) {
        const int l = k * BIN_THREADS + t;
        const float* p = c1 + (size_t)l * (NB * CC) + n * CC;
        x[k] = p[0]; y[k] = p[1]; z[k] = p[2];
        cell[k] = cell_of(x[k], y[k], z[k]);
        atomicAdd(&hist[cell[k]], 1u);
    }
    __syncthreads();

    // Exclusive prefix over 4096 counts: 8/thread -> warp scan -> warp sums.
    const int NPT = NC / BIN_THREADS;  // 8
    unsigned int loc[NPT], s = 0;
#pragma unroll
    for (int j = 0; j < NPT; j++) { loc[j] = hist[t * NPT + j]; s += loc[j]; }
    unsigned int v = s;
#pragma unroll
    for (int o = 1; o < 32; o <<= 1) {
        unsigned int u = __shfl_up_sync(0xffffffffu, v, o);
        if ((t & 31) >= o) v += u;
    }
    const unsigned int excl = v - s;
    if ((t & 31) == 31) wsum[t >> 5] = v;
    __syncthreads();
    if (t < BIN_THREADS / 32) {
        unsigned int w = wsum[t], vv = w;
#pragma unroll
        for (int o = 1; o < BIN_THREADS / 32; o <<= 1) {
            unsigned int u = __shfl_up_sync((1u << (BIN_THREADS / 32)) - 1u, vv, o);
            if (t >= o) vv += u;
        }
        wsum[t] = vv - w;
    }
    __syncthreads();
    unsigned int base = wsum[t >> 5] + excl;
#pragma unroll
    for (int j = 0; j < NPT; j++) {
        const unsigned int tmp = loc[j];
        hist[t * NPT + j] = base;                       // cursor for scatter
        g_cs[n][t * NPT + j] = (unsigned short)base;    // exclusive start
        base += tmp;
    }
    if (t == 0) g_cs[n][NC] = (unsigned short)L1D;
    __syncthreads();

    // Scatter refs; .w carries the ORIGINAL index bits (sr recomputed later
    // with the identical sumsq => bit-identical).
#pragma unroll
    for (int k = 0; k < REFS_PER_T; k++) {
        const int l = k * BIN_THREADS + t;
        const unsigned int pos = atomicAdd(&hist[cell[k]], 1u);
        g_ref4[n][pos] = make_float4(x[k], y[k], z[k], __uint_as_float((unsigned)l));
    }
}

// Kernel 2: WARP-PER-QUERY ring search. Lane j owns cell j of the
// (2r+1)^3 neighborhood; packed-key butterfly reduce gives argmin with
// first-original-index tie semantics. Results staged, written coalesced.
#define SMEM_R 0
#define SMEM_S 65536                       // u16[NC+1] = 8194 -> pad 8208
#define SMEM_Q (SMEM_S + 8208)             // float4[QCH] = 2048
#define SMEM_RES (SMEM_Q + QCH * 16)       // float[QCH] = 512
#define SMEM_TOTAL_B (SMEM_RES + QCH * 4)  // 76304

__global__ __launch_bounds__(S_THREADS)
void nn_search(const float* __restrict__ c2, float* __restrict__ out) {
    extern __shared__ char dyn[];
    float4* sR = (float4*)(dyn + SMEM_R);
    unsigned short* sS = (unsigned short*)(dyn + SMEM_S);
    float4* sQ = (float4*)(dyn + SMEM_Q);
    float* sRes = (float*)(dyn + SMEM_RES);

    const int qc = blockIdx.x;
    const int n  = blockIdx.y;
    const int t  = threadIdx.x;

    for (int i = t; i < L1D; i += S_THREADS) sR[i] = g_ref4[n][i];
    for (int i = t; i <= NC; i += S_THREADS) sS[i] = g_cs[n][i];
    for (int i = t; i < QCH; i += S_THREADS) {
        const float* p = c2 + (size_t)(qc * QCH + i) * (NB * CC) + n * CC;
        const float x = p[0], y = p[1], z = p[2];
        sQ[i] = make_float4(x, y, z, sumsq(x, y, z));
    }
    __syncthreads();

    const int w = t >> 5, lane = t & 31;

    for (int qi = 0; qi < QPW; qi++) {
        const int ql = w * QPW + qi;
        const float4 q = sQ[ql];  // broadcast LDS
        const int cx = min(G - 1, max(0, (int)(q.x * (float)G)));
        const int cy = min(G - 1, max(0, (int)(q.y * (float)G)));
        const int cz = min(G - 1, max(0, (int)(q.z * (float)G)));

        unsigned long long best = ~0ull;
        bool done = false;

        for (int r = 1; r <= 2 && !done; r++) {
            const int nr = 2 * r + 1;
            const int ncells = nr * nr * nr;  // 27 or 125
            for (int cb = lane; cb < ncells; cb += 32) {
                const int dz = cb / (nr * nr) - r;
                const int rem = cb % (nr * nr);
                const int dy = rem / nr - r;
                const int dx = rem % nr - r;
                const int x2 = cx + dx, y2 = cy + dy, z2 = cz + dz;
                if ((unsigned)x2 < G && (unsigned)y2 < G && (unsigned)z2 < G) {
                    const int c = (z2 * G + y2) * G + x2;
                    const unsigned s = sS[c], e = sS[c + 1];
                    for (unsigned i = s; i < e; i++) {
                        const float4 rv = sR[i];
                        const float sr = sumsq(rv.x, rv.y, rv.z);
                        const float d = d2ref(q.x, q.y, q.z, q.w,
                                              rv.x, rv.y, rv.z, sr);
                        const unsigned u = __float_as_uint(d);
                        const unsigned mono =
                            (u & 0x80000000u) ? ~u : (u | 0x80000000u);
                        const unsigned long long key =
                            ((unsigned long long)mono << 32) |
                            (unsigned long long)__float_as_uint(rv.w);
                        if (key < best) best = key;  // (d2, oidx) lex min
                    }
                }
            }
#pragma unroll
            for (int o = 16; o; o >>= 1) {
                const unsigned long long ob = __shfl_xor_sync(0xffffffffu, best, o);
                if (ob < best) best = ob;
            }
            // Unexamined cells hold points with fl-d2 > (r*h)^2 - 1.2e-6;
            // margin 4e-6 => no bit-equal candidate outside scanned region.
            const unsigned mono = (unsigned)(best >> 32);
            const float m = (mono & 0x80000000u)
                                ? __uint_as_float(mono ^ 0x80000000u)
                                : __uint_as_float(~mono);
            const float bnd = (float)r * (1.0f / (float)G);
            done = (m <= bnd * bnd * 0.999f - 4e-6f);  // NaN-safe: false
        }
        if (!done) {  // exhaustive fallback (probability ~0, correctness only)
            for (int i = lane; i < L1D; i += 32) {
                const float4 rv = sR[i];
                const float sr = sumsq(rv.x, rv.y, rv.z);
                const float d = d2ref(q.x, q.y, q.z, q.w, rv.x, rv.y, rv.z, sr);
                const unsigned u = __float_as_uint(d);
                const unsigned mono = (u & 0x80000000u) ? ~u : (u | 0x80000000u);
                const unsigned long long key =
                    ((unsigned long long)mono << 32) |
                    (unsigned long long)__float_as_uint(rv.w);
                if (key < best) best = key;
            }
#pragma unroll
            for (int o = 16; o; o >>= 1) {
                const unsigned long long ob = __shfl_xor_sync(0xffffffffu, best, o);
                if (ob < best) best = ob;
            }
        }
        if (lane == 0)
            sRes[ql] = (float)(unsigned)(best & 0xffffffffull);  // orig index
    }
    __syncthreads();

    // Coalesced output: o = l2i*NB + n. Indices <= 4095 exact in fp32.
    for (int i = t; i < QCH; i += S_THREADS) {
        const int o = (qc * QCH + i) * NB + n;
        out[o] = sRes[i];                // clusters, [L2, N] flat
        out[TOT + o] = (float)n;         // batch indices, [L2, N] flat
    }
}

extern "C" void kernel_launch(void* const* d_in, const int* in_sizes, int n_in,
                              void* d_out, int out_size) {
    const float* c1 = (const float*)d_in[0];  // coords1 [L1, N, C]
    const float* c2 = (const float*)d_in[1];  // coords2 [L2, N, C]
    float* out = (float*)d_out;

    static int smem_set = 0;
    if (!smem_set) {
        cudaFuncSetAttribute(nn_search,
                             cudaFuncAttributeMaxDynamicSharedMemorySize,
                             SMEM_TOTAL_B);
        smem_set = 1;
    }

    nn_bin<<<NB, BIN_THREADS>>>(c1);
    dim3 grid(QSPLIT, NB);
    nn_search<<<grid, S_THREADS, SMEM_TOTAL_B>>>(c2, out);
}

// round 13
// speedup vs baseline: 1.2772x; 1.2772x over previous
#include <cuda_runtime.h>
#include <cstdint>

#define L1D 4096
#define L2D 4096
#define NB 8
#define CC 3
#define TOT (NB * L2D)      // 32768 outputs per half
#define G 16
#define NC (G * G * G)      // 4096 cells
#define BIN_THREADS 512
#define REFS_PER_T (L1D / BIN_THREADS)  // 8
#define SLANES 8                         // lanes cooperating per query
#define QPWARP (32 / SLANES)             // 4 queries per warp
#define S_THREADS 256                    // 8 warps per CTA
#define QCH ((S_THREADS / 32) * QPWARP)  // 32 queries per CTA
#define QSPLIT (L2D / QCH)               // 128

// Binned refs per batch: (x, y, z, oidx-bits) + cell starts.
__device__ float4         g_ref4[NB][L1D];
__device__ unsigned short g_cs[NB][NC + 1];

// Proven bit-exact XLA chain (rounds 8/10/11/12 passed with rel_err 0.0):
//   sr/sq = fl(fl(x*x + y*y) + z*z)     (mul/add, NO fma)
//   dot   = fma(qz,rz, fma(qy,ry, mul(qx,rx)))
//   d2    = fma(dot, -2, add(sq, sr))
static __device__ __forceinline__ float sumsq(float x, float y, float z) {
    return __fadd_rn(__fadd_rn(__fmul_rn(x, x), __fmul_rn(y, y)),
                     __fmul_rn(z, z));
}
static __device__ __forceinline__ float d2ref(float qx, float qy, float qz,
                                              float sq, float rx, float ry,
                                              float rz, float sr) {
    const float dot = __fmaf_rn(qz, rz, __fmaf_rn(qy, ry, __fmul_rn(qx, rx)));
    return __fmaf_rn(dot, -2.0f, __fadd_rn(sq, sr));
}
static __device__ __forceinline__ int cell_of(float x, float y, float z) {
    int cx = min(G - 1, max(0, (int)(x * (float)G)));
    int cy = min(G - 1, max(0, (int)(y * (float)G)));
    int cz = min(G - 1, max(0, (int)(z * (float)G)));
    return (cz * G + cy) * G + cx;
}
// (monotonic d2, original index) packed key: lexicographic u64 min ==
// (min d2, then min ORIGINAL index) => first-occurrence argmin semantics,
// independent of scatter order. Handles negative-zero/negative d2 safely.
static __device__ __forceinline__ unsigned long long mkkey(float d, float w) {
    const unsigned u = __float_as_uint(d);
    const unsigned mono = (u & 0x80000000u) ? ~u : (u | 0x80000000u);
    return ((unsigned long long)mono << 32) | (unsigned long long)__float_as_uint(w);
}
static __device__ __forceinline__ float keyval(unsigned long long k) {
    const unsigned mono = (unsigned)(k >> 32);
    return (mono & 0x80000000u) ? __uint_as_float(mono ^ 0x80000000u)
                                : __uint_as_float(~mono);
}

// Kernel 1: per-batch counting sort of refs into 16^3 cells (one CTA/batch).
__global__ __launch_bounds__(BIN_THREADS)
void nn_bin(const float* __restrict__ c1) {
    __shared__ unsigned int hist[NC];
    __shared__ unsigned int wsum[BIN_THREADS / 32];
    const int n = blockIdx.x;
    const int t = threadIdx.x;

    for (int i = t; i < NC; i += BIN_THREADS) hist[i] = 0;
    __syncthreads();

    float x[REFS_PER_T], y[REFS_PER_T], z[REFS_PER_T];
    int cell[REFS_PER_T];
#pragma unroll
    for (int k = 0; k < REFS_PER_T; k++) {
        const int l = k * BIN_THREADS + t;
        const float* p = c1 + (size_t)l * (NB * CC) + n * CC;
        x[k] = p[0]; y[k] = p[1]; z[k] = p[2];
        cell[k] = cell_of(x[k], y[k], z[k]);
        atomicAdd(&hist[cell[k]], 1u);
    }
    __syncthreads();

    // Exclusive prefix over 4096 counts: 8/thread -> warp scan -> warp sums.
    const int NPT = NC / BIN_THREADS;  // 8
    unsigned int loc[NPT], s = 0;
#pragma unroll
    for (int j = 0; j < NPT; j++) { loc[j] = hist[t * NPT + j]; s += loc[j]; }
    unsigned int v = s;
#pragma unroll
    for (int o = 1; o < 32; o <<= 1) {
        unsigned int u = __shfl_up_sync(0xffffffffu, v, o);
        if ((t & 31) >= o) v += u;
    }
    const unsigned int excl = v - s;
    if ((t & 31) == 31) wsum[t >> 5] = v;
    __syncthreads();
    if (t < BIN_THREADS / 32) {
        unsigned int w = wsum[t], vv = w;
#pragma unroll
        for (int o = 1; o < BIN_THREADS / 32; o <<= 1) {
            unsigned int u = __shfl_up_sync((1u << (BIN_THREADS / 32)) - 1u, vv, o);
            if (t >= o) vv += u;
        }
        wsum[t] = vv - w;
    }
    __syncthreads();
    unsigned int base = wsum[t >> 5] + excl;
#pragma unroll
    for (int j = 0; j < NPT; j++) {
        const unsigned int tmp = loc[j];
        hist[t * NPT + j] = base;                       // cursor for scatter
        g_cs[n][t * NPT + j] = (unsigned short)base;    // exclusive start
        base += tmp;
    }
    if (t == 0) g_cs[n][NC] = (unsigned short)L1D;
    __syncthreads();

    // Scatter refs; .w carries ORIGINAL index bits (sr recomputed later with
    // the identical sumsq => bit-identical d2 chain).
#pragma unroll
    for (int k = 0; k < REFS_PER_T; k++) {
        const int l = k * BIN_THREADS + t;
        const unsigned int pos = atomicAdd(&hist[cell[k]], 1u);
        g_ref4[n][pos] = make_float4(x[k], y[k], z[k], __uint_as_float((unsigned)l));
    }
}

// Kernel 2: 8-LANE-PER-QUERY ring search, zero SMEM, refs/starts via
// L1-cached LDG. Group control flow is uniform (all 8 lanes share a query)
// so group-masked shuffles are legal even when groups diverge in a warp.
__global__ __launch_bounds__(S_THREADS)
void nn_search(const float* __restrict__ c2, float* __restrict__ out) {
    const int qc = blockIdx.x;
    const int n  = blockIdx.y;
    const int t  = threadIdx.x;
    const int warp = t >> 5, lane = t & 31;
    const int g = lane >> 3, sub = lane & 7;
    const unsigned gmask = 0xFFu << (g * 8);
    const int ql  = warp * QPWARP + g;
    const int l2i = qc * QCH + ql;

    const float4* __restrict__ pR = &g_ref4[n][0];
    const unsigned short* __restrict__ pS = &g_cs[n][0];

    const float* p = c2 + (size_t)l2i * (NB * CC) + n * CC;  // 8-lane broadcast
    const float qx = p[0], qy = p[1], qz = p[2];
    const float sq = sumsq(qx, qy, qz);
    const int cx = min(G - 1, max(0, (int)(qx * (float)G)));
    const int cy = min(G - 1, max(0, (int)(qy * (float)G)));
    const int cz = min(G - 1, max(0, (int)(qz * (float)G)));

    unsigned long long best = ~0ull;

    // ---- r = 1: 27 cells, lane sub takes cells sub, sub+8, ... (<=4) ----
#pragma unroll
    for (int cb = sub; cb < 27; cb += SLANES) {
        const int dz = cb / 9 - 1, rem = cb % 9;
        const int dy = rem / 3 - 1, dx = rem % 3 - 1;
        const int x2 = cx + dx, y2 = cy + dy, z2 = cz + dz;
        if ((unsigned)x2 < G && (unsigned)y2 < G && (unsigned)z2 < G) {
            const int c = (z2 * G + y2) * G + x2;
            const unsigned s = pS[c], e = pS[c + 1];
            for (unsigned i = s; i < e; i++) {
                const float4 rv = pR[i];
                const float sr = sumsq(rv.x, rv.y, rv.z);
                const float d = d2ref(qx, qy, qz, sq, rv.x, rv.y, rv.z, sr);
                const unsigned long long key = mkkey(d, rv.w);
                if (key < best) best = key;
            }
        }
    }
#pragma unroll
    for (int o = SLANES / 2; o; o >>= 1) {
        const unsigned long long ob = __shfl_xor_sync(gmask, best, o);
        if (ob < best) best = ob;
    }
    // Unexamined cells (Chebyshev > r) hold points with fl-d2 > (r*h)^2-1.2e-6;
    // margin 4e-6 => no bit-equal candidate outside the scanned region.
    const float h = 1.0f / (float)G;
    bool done = (keyval(best) <= h * h * 0.999f - 4e-6f);  // NaN-safe: false

    if (!done) {
        // ---- r = 2: rescan full 5^3 neighborhood (dup evals harmless) ----
#pragma unroll 4
        for (int cb = sub; cb < 125; cb += SLANES) {
            const int dz = cb / 25 - 2, rem = cb % 25;
            const int dy = rem / 5 - 2, dx = rem % 5 - 2;
            const int x2 = cx + dx, y2 = cy + dy, z2 = cz + dz;
            if ((unsigned)x2 < G && (unsigned)y2 < G && (unsigned)z2 < G) {
                const int c = (z2 * G + y2) * G + x2;
                const unsigned s = pS[c], e = pS[c + 1];
                for (unsigned i = s; i < e; i++) {
                    const float4 rv = pR[i];
                    const float sr = sumsq(rv.x, rv.y, rv.z);
                    const float d = d2ref(qx, qy, qz, sq, rv.x, rv.y, rv.z, sr);
                    const unsigned long long key = mkkey(d, rv.w);
                    if (key < best) best = key;
                }
            }
        }
#pragma unroll
        for (int o = SLANES / 2; o; o >>= 1) {
            const unsigned long long ob = __shfl_xor_sync(gmask, best, o);
            if (ob < best) best = ob;
        }
        const float b2 = 2.0f * h;
        done = (keyval(best) <= b2 * b2 * 0.999f - 4e-6f);

        if (!done) {  // exhaustive fallback (probability ~0, correctness only)
            for (int i = sub; i < L1D; i += SLANES) {
                const float4 rv = pR[i];
                const float sr = sumsq(rv.x, rv.y, rv.z);
                const float d = d2ref(qx, qy, qz, sq, rv.x, rv.y, rv.z, sr);
                const unsigned long long key = mkkey(d, rv.w);
                if (key < best) best = key;
            }
#pragma unroll
            for (int o = SLANES / 2; o; o >>= 1) {
                const unsigned long long ob = __shfl_xor_sync(gmask, best, o);
                if (ob < best) best = ob;
            }
        }
    }

    if (sub == 0) {
        const int o = l2i * NB + n;
        out[o] = (float)(unsigned)(best & 0xffffffffull);  // cluster index
        out[TOT + o] = (float)n;                           // batch index
    }
}

extern "C" void kernel_launch(void* const* d_in, const int* in_sizes, int n_in,
                              void* d_out, int out_size) {
    const float* c1 = (const float*)d_in[0];  // coords1 [L1, N, C]
    const float* c2 = (const float*)d_in[1];  // coords2 [L2, N, C]
    float* out = (float*)d_out;

    nn_bin<<<NB, BIN_THREADS>>>(c1);
    dim3 grid(QSPLIT, NB);
    nn_search<<<grid, S_THREADS>>>(c2, out);
}

// round 14
// speedup vs baseline: 1.6472x; 1.2897x over previous
#include <cuda_runtime.h>
#include <cstdint>

#define L1D 4096
#define L2D 4096
#define NB 8
#define CC 3
#define TOT (NB * L2D)      // 32768 outputs per half
#define G 16
#define NC (G * G * G)      // 4096 cells
#define BIN_THREADS 1024
#define REFS_PER_T (L1D / BIN_THREADS)  // 4
#define SLANES 8                         // lanes cooperating per query
#define QPWARP (32 / SLANES)             // 4 queries per warp
#define S_THREADS 256                    // 8 warps per CTA
#define QCH ((S_THREADS / 32) * QPWARP)  // 32 queries per CTA
#define QSPLIT (L2D / QCH)               // 128

// Binned refs per batch: (x, y, z, oidx-bits) + cell starts.
__device__ float4         g_ref4[NB][L1D];
__device__ unsigned short g_cs[NB][NC + 1];

// Proven bit-exact XLA chain (rounds 8/10/11/12/13 passed, rel_err 0.0):
//   sr/sq = fl(fl(x*x + y*y) + z*z)     (mul/add, NO fma)
//   dot   = fma(qz,rz, fma(qy,ry, mul(qx,rx)))
//   d2    = fma(dot, -2, add(sq, sr))
static __device__ __forceinline__ float sumsq(float x, float y, float z) {
    return __fadd_rn(__fadd_rn(__fmul_rn(x, x), __fmul_rn(y, y)),
                     __fmul_rn(z, z));
}
static __device__ __forceinline__ float d2ref(float qx, float qy, float qz,
                                              float sq, float rx, float ry,
                                              float rz, float sr) {
    const float dot = __fmaf_rn(qz, rz, __fmaf_rn(qy, ry, __fmul_rn(qx, rx)));
    return __fmaf_rn(dot, -2.0f, __fadd_rn(sq, sr));
}
static __device__ __forceinline__ int cell_of(float x, float y, float z) {
    int cx = min(G - 1, max(0, (int)(x * (float)G)));
    int cy = min(G - 1, max(0, (int)(y * (float)G)));
    int cz = min(G - 1, max(0, (int)(z * (float)G)));
    return (cz * G + cy) * G + cx;
}
// (monotonic d2, original index) packed key: lexicographic u64 min ==
// (min d2, then min ORIGINAL index) => first-occurrence argmin semantics,
// independent of scatter order.
static __device__ __forceinline__ unsigned long long mkkey(float d, float w) {
    const unsigned u = __float_as_uint(d);
    const unsigned mono = (u & 0x80000000u) ? ~u : (u | 0x80000000u);
    return ((unsigned long long)mono << 32) | (unsigned long long)__float_as_uint(w);
}
static __device__ __forceinline__ float keyval(unsigned long long k) {
    const unsigned mono = (unsigned)(k >> 32);
    return (mono & 0x80000000u) ? __uint_as_float(mono ^ 0x80000000u)
                                : __uint_as_float(~mono);
}

// Kernel 1: per-batch counting sort of refs into 16^3 cells (one CTA/batch).
__global__ __launch_bounds__(BIN_THREADS)
void nn_bin(const float* __restrict__ c1) {
    __shared__ unsigned int hist[NC];
    __shared__ unsigned int wsum[BIN_THREADS / 32];
    const int n = blockIdx.x;
    const int t = threadIdx.x;

    for (int i = t; i < NC; i += BIN_THREADS) hist[i] = 0;
    __syncthreads();

    float x[REFS_PER_T], y[REFS_PER_T], z[REFS_PER_T];
    int cell[REFS_PER_T];
#pragma unroll
    for (int k = 0; k < REFS_PER_T; k++) {
        const int l = k * BIN_THREADS + t;
        const float* p = c1 + (size_t)l * (NB * CC) + n * CC;
        x[k] = p[0]; y[k] = p[1]; z[k] = p[2];
        cell[k] = cell_of(x[k], y[k], z[k]);
        atomicAdd(&hist[cell[k]], 1u);
    }
    __syncthreads();

    // Exclusive prefix over 4096 counts: 4/thread -> warp scan -> warp sums.
    const int NPT = NC / BIN_THREADS;  // 4
    unsigned int loc[NPT], s = 0;
#pragma unroll
    for (int j = 0; j < NPT; j++) { loc[j] = hist[t * NPT + j]; s += loc[j]; }
    unsigned int v = s;
#pragma unroll
    for (int o = 1; o < 32; o <<= 1) {
        unsigned int u = __shfl_up_sync(0xffffffffu, v, o);
        if ((t & 31) >= o) v += u;
    }
    const unsigned int excl = v - s;
    if ((t & 31) == 31) wsum[t >> 5] = v;
    __syncthreads();
    if (t < BIN_THREADS / 32) {  // 32 warp sums -> one warp scans them
        unsigned int w = wsum[t], vv = w;
#pragma unroll
        for (int o = 1; o < 32; o <<= 1) {
            unsigned int u = __shfl_up_sync(0xffffffffu, vv, o);
            if (t >= o) vv += u;
        }
        wsum[t] = vv - w;
    }
    __syncthreads();
    unsigned int base = wsum[t >> 5] + excl;
#pragma unroll
    for (int j = 0; j < NPT; j++) {
        const unsigned int tmp = loc[j];
        hist[t * NPT + j] = base;                       // cursor for scatter
        g_cs[n][t * NPT + j] = (unsigned short)base;    // exclusive start
        base += tmp;
    }
    if (t == 0) g_cs[n][NC] = (unsigned short)L1D;
    __syncthreads();

    // Scatter refs; .w carries ORIGINAL index bits (sr recomputed later with
    // the identical sumsq => bit-identical d2 chain).
#pragma unroll
    for (int k = 0; k < REFS_PER_T; k++) {
        const int l = k * BIN_THREADS + t;
        const unsigned int pos = atomicAdd(&hist[cell[k]], 1u);
        g_ref4[n][pos] = make_float4(x[k], y[k], z[k], __uint_as_float((unsigned)l));
    }
}

// Candidate scan over a contiguous ref range (cells are x-contiguous after
// the counting sort => one (z,y) row of the neighborhood = one range).
static __device__ __forceinline__ void scan_range(
    const float4* __restrict__ pR, unsigned s, unsigned e,
    float qx, float qy, float qz, float sq, unsigned long long& best) {
    for (unsigned i = s; i < e; i++) {
        const float4 rv = pR[i];
        const float sr = sumsq(rv.x, rv.y, rv.z);
        const float d = d2ref(qx, qy, qz, sq, rv.x, rv.y, rv.z, sr);
        const unsigned long long key = mkkey(d, rv.w);
        if (key < best) best = key;
    }
}

// Kernel 2: 8-LANE-PER-QUERY ring search over CONTIGUOUS X-ROWS.
// r=1: 9 rows; r=2: 25 rows. Zero SMEM; refs/starts via L1-cached LDG.
// Group control flow is uniform (8 lanes share a query).
__global__ __launch_bounds__(S_THREADS)
void nn_search(const float* __restrict__ c2, float* __restrict__ out) {
    const int qc = blockIdx.x;
    const int n  = blockIdx.y;
    const int t  = threadIdx.x;
    const int warp = t >> 5, lane = t & 31;
    const int g = lane >> 3, sub = lane & 7;
    const unsigned gmask = 0xFFu << (g * 8);
    const int ql  = warp * QPWARP + g;
    const int l2i = qc * QCH + ql;

    const float4* __restrict__ pR = &g_ref4[n][0];
    const unsigned short* __restrict__ pS = &g_cs[n][0];

    const float* p = c2 + (size_t)l2i * (NB * CC) + n * CC;  // 8-lane broadcast
    const float qx = p[0], qy = p[1], qz = p[2];
    const float sq = sumsq(qx, qy, qz);
    const int cx = min(G - 1, max(0, (int)(qx * (float)G)));
    const int cy = min(G - 1, max(0, (int)(qy * (float)G)));
    const int cz = min(G - 1, max(0, (int)(qz * (float)G)));

    unsigned long long best = ~0ull;

    // ---- r = 1: 9 (z,y)-rows, each a contiguous x-range [xlo..xhi] ----
    {
        const int xlo = max(cx - 1, 0), xhi = min(cx + 1, G - 1);
#pragma unroll
        for (int j = sub; j < 9; j += SLANES) {  // lane sub: row sub (+8 for sub=0)
            const int dz = j / 3 - 1, dy = j % 3 - 1;
            const int z2 = cz + dz, y2 = cy + dy;
            if ((unsigned)z2 < G && (unsigned)y2 < G) {
                const int rowb = (z2 * G + y2) * G;
                const unsigned s = pS[rowb + xlo], e = pS[rowb + xhi + 1];
                scan_range(pR, s, e, qx, qy, qz, sq, best);
            }
        }
    }
#pragma unroll
    for (int o = SLANES / 2; o; o >>= 1) {
        const unsigned long long ob = __shfl_xor_sync(gmask, best, o);
        if (ob < best) best = ob;
    }
    // Unexamined cells (Chebyshev > r) hold points with fl-d2 > (r*h)^2-1.2e-6;
    // margin 4e-6 => no bit-equal candidate outside the scanned region.
    const float h = 1.0f / (float)G;
    bool done = (keyval(best) <= h * h * 0.999f - 4e-6f);  // NaN-safe: false

    if (!done) {
        // ---- r = 2: rescan full 5x5 rows x [cx-2..cx+2] (dups harmless) ----
        const int xlo = max(cx - 2, 0), xhi = min(cx + 2, G - 1);
#pragma unroll 4
        for (int j = sub; j < 25; j += SLANES) {
            const int dz = j / 5 - 2, dy = j % 5 - 2;
            const int z2 = cz + dz, y2 = cy + dy;
            if ((unsigned)z2 < G && (unsigned)y2 < G) {
                const int rowb = (z2 * G + y2) * G;
                const unsigned s = pS[rowb + xlo], e = pS[rowb + xhi + 1];
                scan_range(pR, s, e, qx, qy, qz, sq, best);
            }
        }
#pragma unroll
        for (int o = SLANES / 2; o; o >>= 1) {
            const unsigned long long ob = __shfl_xor_sync(gmask, best, o);
            if (ob < best) best = ob;
        }
        const float b2 = 2.0f * h;
        done = (keyval(best) <= b2 * b2 * 0.999f - 4e-6f);

        if (!done) {  // exhaustive fallback (probability ~0, correctness only)
            for (int i = sub; i < L1D; i += SLANES) {
                const float4 rv = pR[i];
                const float sr = sumsq(rv.x, rv.y, rv.z);
                const float d = d2ref(qx, qy, qz, sq, rv.x, rv.y, rv.z, sr);
                const unsigned long long key = mkkey(d, rv.w);
                if (key < best) best = key;
            }
#pragma unroll
            for (int o = SLANES / 2; o; o >>= 1) {
                const unsigned long long ob = __shfl_xor_sync(gmask, best, o);
                if (ob < best) best = ob;
            }
        }
    }

    if (sub == 0) {
        const int o = l2i * NB + n;
        out[o] = (float)(unsigned)(best & 0xffffffffull);  // cluster index
        out[TOT + o] = (float)n;                           // batch index
    }
}

extern "C" void kernel_launch(void* const* d_in, const int* in_sizes, int n_in,
                              void* d_out, int out_size) {
    const float* c1 = (const float*)d_in[0];  // coords1 [L1, N, C]
    const float* c2 = (const float*)d_in[1];  // coords2 [L2, N, C]
    float* out = (float*)d_out;

    nn_bin<<<NB, BIN_THREADS>>>(c1);
    dim3 grid(QSPLIT, NB);
    nn_search<<<grid, S_THREADS>>>(c2, out);
}